// round 4
// baseline (speedup 1.0000x reference)
#include <cuda_runtime.h>
#include <cuda_bf16.h>

#define BATCH 2
#define NSEQ 1024
#define DIM 256
#define PDIM 64
#define MAXREL 32
#define NEMBED (2 * MAXREL + 1)

// Scratch: projections (proj_j has bias pre-added)
__device__ float g_proj_i[BATCH * NSEQ * PDIM];
__device__ float g_proj_j[BATCH * NSEQ * PDIM];

// ---------------------------------------------------------------------------
// Kernel 1: proj_i = single @ W[:256], proj_j = single @ W[256:] + b
// One block per row (b*N + n), 128 threads: t<64 -> proj_i[p], t>=64 -> proj_j[p]
// ---------------------------------------------------------------------------
__global__ __launch_bounds__(128) void proj_kernel(
    const float* __restrict__ single, const float* __restrict__ W,
    const float* __restrict__ bias)
{
    __shared__ float s[DIM];
    const int r = blockIdx.x;
    const int t = threadIdx.x;
    const float* row = single + (size_t)r * DIM;
    s[t] = row[t];
    s[t + 128] = row[t + 128];
    __syncthreads();

    const int p = t & 63;
    const float* Wp = W + (t >= 64 ? DIM * PDIM : 0) + p;
    float acc = 0.f;
#pragma unroll 8
    for (int d = 0; d < DIM; d++)
        acc = fmaf(s[d], Wp[d * PDIM], acc);

    if (t < 64)
        g_proj_i[(size_t)r * PDIM + p] = acc;
    else
        g_proj_j[(size_t)r * PDIM + p] = acc + bias[p];
}

// ---------------------------------------------------------------------------
// Kernel 2: for each (b, i, j):
//   x = proj_i[b,i] + proj_j[b,j]  (bias already folded in)
//   layernorm(64) -> *gamma + beta -> relu -> + embed[clip(j-i)+32]
// Block = (b, i): 256 threads = 8 warps, each warp does 2 pairs at a time
// (16 lanes per pair, float4 per lane). Fully coalesced float4 stores.
// ---------------------------------------------------------------------------
__global__ __launch_bounds__(256) void pair_kernel(
    const float* __restrict__ gamma, const float* __restrict__ beta,
    const float* __restrict__ embed, float* __restrict__ out)
{
    __shared__ float s_embed[NEMBED * PDIM];

    const int i = blockIdx.x;
    const int b = blockIdx.y;

    for (int t = threadIdx.x; t < NEMBED * PDIM; t += 256)
        s_embed[t] = embed[t];

    const int lane = threadIdx.x & 31;
    const int w = threadIdx.x >> 5;
    const int h = lane >> 4;       // which of the 2 pairs in this warp
    const int li = lane & 15;      // lane within the 16-lane pair group

    const float4 a  = *(const float4*)(g_proj_i + ((size_t)(b * NSEQ + i)) * PDIM + li * 4);
    const float4 gm = *(const float4*)(gamma + li * 4);
    const float4 bt = *(const float4*)(beta + li * 4);

    const float* pj = g_proj_j + (size_t)b * NSEQ * PDIM;
    float* outrow = out + ((size_t)(b * NSEQ + i)) * NSEQ * PDIM + li * 4;

    __syncthreads();

    const float inv64 = 1.0f / 64.0f;

#pragma unroll 4
    for (int jb = 0; jb < NSEQ; jb += 16) {
        const int j = jb + w * 2 + h;
        const float4 c = *(const float4*)(pj + (size_t)j * PDIM + li * 4);

        float4 x;
        x.x = a.x + c.x; x.y = a.y + c.y; x.z = a.z + c.z; x.w = a.w + c.w;

        float s = (x.x + x.y) + (x.z + x.w);
        float q = fmaf(x.x, x.x, fmaf(x.y, x.y, fmaf(x.z, x.z, x.w * x.w)));

        // reduce over the 16-lane group (xor offsets < 16 stay in-group)
#pragma unroll
        for (int off = 8; off > 0; off >>= 1) {
            s += __shfl_xor_sync(0xffffffffu, s, off);
            q += __shfl_xor_sync(0xffffffffu, q, off);
        }

        const float mu  = s * inv64;
        const float var = fmaf(q, inv64, -mu * mu);
        const float rinv = rsqrtf(var + 1e-5f);

        const float rgx = rinv * gm.x, rgy = rinv * gm.y;
        const float rgz = rinv * gm.z, rgw = rinv * gm.w;

        float4 y;
        y.x = fmaxf(fmaf(x.x - mu, rgx, bt.x), 0.f);
        y.y = fmaxf(fmaf(x.y - mu, rgy, bt.y), 0.f);
        y.z = fmaxf(fmaf(x.z - mu, rgz, bt.z), 0.f);
        y.w = fmaxf(fmaf(x.w - mu, rgw, bt.w), 0.f);

        int rel = j - i;
        rel = min(max(rel, -MAXREL), MAXREL) + MAXREL;
        const float4 e = *(const float4*)(s_embed + rel * PDIM + li * 4);
        y.x += e.x; y.y += e.y; y.z += e.z; y.w += e.w;

        *(float4*)(outrow + (size_t)j * PDIM) = y;
    }
}

extern "C" void kernel_launch(void* const* d_in, const int* in_sizes, int n_in,
                              void* d_out, int out_size)
{
    const float* single = (const float*)d_in[0];
    const float* W      = (const float*)d_in[1];
    const float* bias   = (const float*)d_in[2];
    const float* gamma  = (const float*)d_in[3];
    const float* beta   = (const float*)d_in[4];
    const float* embed  = (const float*)d_in[5];
    float* out = (float*)d_out;

    proj_kernel<<<BATCH * NSEQ, 128>>>(single, W, bias);

    dim3 grid(NSEQ, BATCH);
    pair_kernel<<<grid, 256>>>(gamma, beta, embed, out);
}